// round 7
// baseline (speedup 1.0000x reference)
#include <cuda_runtime.h>
#include <cuda_bf16.h>
#include <math.h>
#include <stdint.h>

#define Tt 3
#define NB 2
#define HH 360
#define WW 640
#define FF 2
#define HF 720
#define WF 1280
#define PLANE (HF*WF)
#define SRC (HH*WW)

// ---------------- device-global scratch ----------------
__device__ float4 g_fb4[NB*PLANE];            // frame_bicubic, NHWC float4 (fp32)
__device__ float4 g_hw4[NB*PLANE];            // warped history, NHWC float4 (fp32)
__device__ float4 g_ha [NB*PLANE];            // persistent history state
__device__ __nv_bfloat16 g_x0[(size_t)NB*PLANE*8];   // CNN input NHWC bf16
__device__ __nv_bfloat16 g_h1[(size_t)NB*PLANE*64];  // conv1 out NHWC bf16
__device__ __nv_bfloat16 g_h2[(size_t)NB*PLANE*64];  // conv2 out NHWC bf16
__device__ uint4 g_w1f[5*4*32];               // conv1 A fragments [kc][mt][lane]
__device__ uint4 g_w2f[9*4*4*32];             // conv2 A fragments [tap][kt][mt][lane]
__device__ float g_w3p[9*2*64];               // conv3 weights [tap][oc][ic] fp32

// ---------------- helpers ----------------
__device__ __forceinline__ void cubw(float t, float w[4]) {
    const float a = -0.75f;
    float t2 = t*t, t3 = t2*t;
    w[0] = a*(t3 - 2.0f*t2 + t);
    w[1] = (a + 2.0f)*t3 - (a + 3.0f)*t2 + 1.0f;
    float s = 1.0f - t;
    w[2] = (a + 2.0f)*s*s*s - (a + 3.0f)*s*s + 1.0f;
    float u = 2.0f - t;
    w[3] = a*u*u*u - 5.0f*a*u*u + 8.0f*a*u - 4.0f*a;
}

__device__ __forceinline__ float depth_tx(float d) {
    float z = 10.0f / (100.0f - d * 99.9f);
    return (z - 0.1f) * (1.0f / 99.9f);
}

__device__ __forceinline__ uint32_t packbf(float lo, float hi) {
    __nv_bfloat162 h = __floats2bfloat162_rn(lo, hi);
    return *reinterpret_cast<uint32_t*>(&h);
}

__device__ __forceinline__ void mma_bf16(float c[4], uint32_t a0, uint32_t a1,
                                         uint32_t a2, uint32_t a3,
                                         uint32_t b0, uint32_t b1) {
    asm volatile(
        "mma.sync.aligned.m16n8k16.row.col.f32.bf16.bf16.f32 "
        "{%0,%1,%2,%3}, {%4,%5,%6,%7}, {%8,%9}, {%0,%1,%2,%3};\n"
        : "+f"(c[0]), "+f"(c[1]), "+f"(c[2]), "+f"(c[3])
        : "r"(a0), "r"(a1), "r"(a2), "r"(a3), "r"(b0), "r"(b1));
}

// ---------------- weight prepack into MMA A-fragment layouts ----------------
__global__ void prepack_kernel(const float* __restrict__ w1,
                               const float* __restrict__ w2,
                               const float* __restrict__ w3)
{
    int i = blockIdx.x * 256 + threadIdx.x;
    if (i < 4608) {
        // conv2: e = ((tap*4+kt)*4+mt)*32 + lane ; oc = mt*16 + gid
        int lane = i & 31;
        int mt = (i >> 5) & 3;
        int kt = (i >> 7) & 3, tap = i >> 9;
        int gid = lane >> 2, tig = lane & 3;
        int oc = mt*16 + gid;
        int k0 = kt*16 + 2*tig;
        uint4 v;
        v.x = packbf(w2[(oc*64 + k0)*9 + tap],       w2[(oc*64 + k0 + 1)*9 + tap]);
        v.y = packbf(w2[((oc+8)*64 + k0)*9 + tap],   w2[((oc+8)*64 + k0 + 1)*9 + tap]);
        v.z = packbf(w2[(oc*64 + k0 + 8)*9 + tap],   w2[(oc*64 + k0 + 9)*9 + tap]);
        v.w = packbf(w2[((oc+8)*64 + k0 + 8)*9 + tap], w2[((oc+8)*64 + k0 + 9)*9 + tap]);
        g_w2f[i] = v;
    } else if (i < 4608 + 640) {
        // conv1: K = 80 = 5 chunks of (2 taps x 8 ic); tap 9 is zero pad
        int f = i - 4608;
        int lane = f & 31;
        int mt = (f >> 5) & 3;
        int kc = f >> 7;
        int gid = lane >> 2, tig = lane & 3;
        int oc = mt*16 + gid;
        int ic = 2*tig;
        int tlo = 2*kc, thi = 2*kc + 1;
        uint4 v;
        v.x = packbf(w1[(oc*8 + ic)*9 + tlo],     w1[(oc*8 + ic + 1)*9 + tlo]);
        v.y = packbf(w1[((oc+8)*8 + ic)*9 + tlo], w1[((oc+8)*8 + ic + 1)*9 + tlo]);
        if (thi <= 8) {
            v.z = packbf(w1[(oc*8 + ic)*9 + thi],     w1[(oc*8 + ic + 1)*9 + thi]);
            v.w = packbf(w1[((oc+8)*8 + ic)*9 + thi], w1[((oc+8)*8 + ic + 1)*9 + thi]);
        } else { v.z = 0u; v.w = 0u; }
        g_w1f[f] = v;
    } else if (i < 4608 + 640 + 1152) {
        int j = i - 5248;
        int tap = j >> 7, rem = j & 127;
        int oc = rem >> 6, ic = rem & 63;
        g_w3p[j] = w3[(oc*64 + ic)*9 + tap];
    }
}

// ---------------- first step: frame_bicubic + frame_up (+history init) ----------------
__global__ void pre_kernel(const float* __restrict__ frame,
                           const float* __restrict__ depth,
                           const float* __restrict__ jit)
{
    int idx = blockIdx.x * blockDim.x + threadIdx.x;
    if (idx >= NB*PLANE) return;
    int x = idx % WF;
    int y = (idx / WF) % HF;
    int n = idx / PLANE;

    float jx = jit[n*2 + 0];
    float jy = jit[n*2 + 1];

    float gx = (2.0f*x + 1.0f) / (float)WF - 1.0f + 2.0f*(0.5f - jx) / (float)WW;
    float gy = (2.0f*y + 1.0f) / (float)HF - 1.0f + 2.0f*(0.5f - jy) / (float)HH;
    float ix = ((gx + 1.0f) * (float)WW - 1.0f) * 0.5f;
    float iy = ((gy + 1.0f) * (float)HH - 1.0f) * 0.5f;
    float x0 = floorf(ix), y0 = floorf(iy);
    float wx[4], wy[4];
    cubw(ix - x0, wx);
    cubw(iy - y0, wy);
    int xi[4], yi[4];
    #pragma unroll
    for (int i = 0; i < 4; i++) {
        xi[i] = min(max((int)x0 + i - 1, 0), WW - 1);
        yi[i] = min(max((int)y0 + i - 1, 0), HH - 1);
    }

    const float* fr = frame + n * 3 * SRC;
    const float* dp = depth + n * SRC;
    float a0 = 0.f, a1 = 0.f, a2 = 0.f, a3 = 0.f;
    #pragma unroll
    for (int i = 0; i < 4; i++) {
        int ro = yi[i] * WW;
        #pragma unroll
        for (int j = 0; j < 4; j++) {
            float wgt = wy[i] * wx[j];
            int off = ro + xi[j];
            a0 += wgt * fr[off];
            a1 += wgt * fr[SRC + off];
            a2 += wgt * fr[2*SRC + off];
            a3 += wgt * depth_tx(dp[off]);
        }
    }
    int o = y * WF + x;
    g_fb4[n * PLANE + o] = make_float4(a0, a1, a2, a3);
    g_hw4[n * PLANE + o] = make_float4(a0, a1, a2, a3);

    int jxi = (int)floorf(jx * (float)FF);
    int jyi = (int)floorf(jy * (float)FF);
    int ux = x - jxi, uy = y - jyi;
    float u0 = 0.f, u1 = 0.f, u2 = 0.f, u3 = 0.f;
    if (ux >= 0 && uy >= 0 && (ux % FF) == 0 && (uy % FF) == 0) {
        int off = (uy / FF) * WW + (ux / FF);
        u0 = fr[off]; u1 = fr[SRC + off]; u2 = fr[2*SRC + off];
        u3 = depth_tx(dp[off]);
    }
    __nv_bfloat162* x0p = (__nv_bfloat162*)(g_x0 + ((size_t)n * PLANE + o) * 8);
    x0p[0] = __floats2bfloat162_rn(u0, u1);
    x0p[1] = __floats2bfloat162_rn(u2, u3);
    x0p[2] = __floats2bfloat162_rn(a0, a1);
    x0p[3] = __floats2bfloat162_rn(a2, a3);
}

// ---------------- later steps: pre + history warp fused ----------------
__global__ void prewarp_kernel(const float* __restrict__ frame,
                               const float* __restrict__ depth,
                               const float* __restrict__ jit,
                               const float* __restrict__ mv)
{
    int idx = blockIdx.x * blockDim.x + threadIdx.x;
    if (idx >= NB*PLANE) return;
    int x = idx % WF;
    int y = (idx / WF) % HF;
    int n = idx / PLANE;

    float jx = jit[n*2 + 0];
    float jy = jit[n*2 + 1];

    // ---- frame_bicubic ----
    float gx = (2.0f*x + 1.0f) / (float)WF - 1.0f + 2.0f*(0.5f - jx) / (float)WW;
    float gy = (2.0f*y + 1.0f) / (float)HF - 1.0f + 2.0f*(0.5f - jy) / (float)HH;
    float ix = ((gx + 1.0f) * (float)WW - 1.0f) * 0.5f;
    float iy = ((gy + 1.0f) * (float)HH - 1.0f) * 0.5f;
    float x0f_ = floorf(ix), y0f_ = floorf(iy);
    float wx[4], wy[4];
    cubw(ix - x0f_, wx);
    cubw(iy - y0f_, wy);
    int xi[4], yi[4];
    #pragma unroll
    for (int i = 0; i < 4; i++) {
        xi[i] = min(max((int)x0f_ + i - 1, 0), WW - 1);
        yi[i] = min(max((int)y0f_ + i - 1, 0), HH - 1);
    }
    const float* fr = frame + n * 3 * SRC;
    const float* dp = depth + n * SRC;
    float a0 = 0.f, a1 = 0.f, a2 = 0.f, a3 = 0.f;
    #pragma unroll
    for (int i = 0; i < 4; i++) {
        int ro = yi[i] * WW;
        #pragma unroll
        for (int j = 0; j < 4; j++) {
            float wgt = wy[i] * wx[j];
            int off = ro + xi[j];
            a0 += wgt * fr[off];
            a1 += wgt * fr[SRC + off];
            a2 += wgt * fr[2*SRC + off];
            a3 += wgt * depth_tx(dp[off]);
        }
    }
    int o = y * WF + x;
    g_fb4[n * PLANE + o] = make_float4(a0, a1, a2, a3);

    // ---- frame_up ----
    int jxi = (int)floorf(jx * (float)FF);
    int jyi = (int)floorf(jy * (float)FF);
    int ux = x - jxi, uy = y - jyi;
    float u0 = 0.f, u1 = 0.f, u2 = 0.f, u3 = 0.f;
    if (ux >= 0 && uy >= 0 && (ux % FF) == 0 && (uy % FF) == 0) {
        int off = (uy / FF) * WW + (ux / FF);
        u0 = fr[off]; u1 = fr[SRC + off]; u2 = fr[2*SRC + off];
        u3 = depth_tx(dp[off]);
    }
    __nv_bfloat162* x0p = (__nv_bfloat162*)(g_x0 + ((size_t)n * PLANE + o) * 8);
    x0p[0] = __floats2bfloat162_rn(u0, u1);
    x0p[1] = __floats2bfloat162_rn(u2, u3);

    // ---- history warp ----
    float cx = fmaxf(((float)x + 0.5f) / (float)FF - 0.5f, 0.0f);
    float cy = fmaxf(((float)y + 0.5f) / (float)FF - 0.5f, 0.0f);
    float fx0 = floorf(cx), fy0 = floorf(cy);
    float tx = cx - fx0, ty = cy - fy0;
    int mx0 = min(max((int)fx0, 0), WW - 1);
    int mx1 = min((int)fx0 + 1, WW - 1);
    int my0 = min(max((int)fy0, 0), HH - 1);
    int my1 = min((int)fy0 + 1, HH - 1);

    const float* m = mv + (size_t)n * SRC * 2;
    int i00 = (my0 * WW + mx0) * 2, i01 = (my0 * WW + mx1) * 2;
    int i10 = (my1 * WW + mx0) * 2, i11 = (my1 * WW + mx1) * 2;
    float mvx = (m[i00] * (1.f - tx) + m[i01] * tx) * (1.f - ty)
              + (m[i10] * (1.f - tx) + m[i11] * tx) * ty;
    float mvy = (m[i00+1] * (1.f - tx) + m[i01+1] * tx) * (1.f - ty)
              + (m[i10+1] * (1.f - tx) + m[i11+1] * tx) * ty;

    float4 res;
    bool oob = (mvx > 1.0f) || (mvx < -1.0f) || (mvy > 1.0f) || (mvy < -1.0f);
    if (oob) {
        res = make_float4(a0, a1, a2, a3);
    } else {
        float ixf = ((mvx + 1.0f) * (float)WF - 1.0f) * 0.5f;
        float iyf = ((mvy + 1.0f) * (float)HF - 1.0f) * 0.5f;
        float wx2[4], wy2[4];
        float x0w = floorf(ixf), y0w = floorf(iyf);
        cubw(ixf - x0w, wx2);
        cubw(iyf - y0w, wy2);
        int xj[4], yj[4];
        #pragma unroll
        for (int i = 0; i < 4; i++) {
            xj[i] = min(max((int)x0w + i - 1, 0), WF - 1);
            yj[i] = min(max((int)y0w + i - 1, 0), HF - 1);
        }
        const float4* hp = g_ha + n * PLANE;
        float b0 = 0.f, b1 = 0.f, b2 = 0.f, b3 = 0.f;
        #pragma unroll
        for (int i = 0; i < 4; i++) {
            int ro = yj[i] * WF;
            #pragma unroll
            for (int j = 0; j < 4; j++) {
                float wgt = wy2[i] * wx2[j];
                float4 v = hp[ro + xj[j]];
                b0 += wgt * v.x; b1 += wgt * v.y; b2 += wgt * v.z; b3 += wgt * v.w;
            }
        }
        res = make_float4(b0, b1, b2, b3);
    }
    g_hw4[n * PLANE + o] = res;
    x0p[2] = __floats2bfloat162_rn(res.x, res.y);
    x0p[3] = __floats2bfloat162_rn(res.z, res.w);
}

// ================= conv1: 8 -> 64, ReLU, bf16 MMA (K=80 padded) =================
// tile 32x8, 8 warps: warp = output row, M=64 per warp (mt 0..3), N=32 (nt 0..3)
__global__ void __launch_bounds__(256, 2) conv1_kernel(const float* __restrict__ bias)
{
    __shared__ uint4 s_x0[340];   // [10 rows][34 cols] x 8ch bf16 = 16B/px

    const int tid = threadIdx.x;
    const int lane = tid & 31, ly = tid >> 5;
    const int gid = lane >> 2, tig = lane & 3;
    const int n = blockIdx.z;
    const int x0t = blockIdx.x * 32, y0t = blockIdx.y * 8;

    for (int i = tid; i < 340; i += 256) {
        int r = i / 34, c = i - r * 34;
        int gy = min(max(y0t - 1 + r, 0), HF - 1);
        int gx = min(max(x0t - 1 + c, 0), WF - 1);
        s_x0[i] = *(const uint4*)(g_x0 + ((size_t)n * PLANE + gy * WF + gx) * 8);
    }
    __syncthreads();

    float acc[4][4][4] = {};
    const uint32_t* sp = (const uint32_t*)s_x0;

    #pragma unroll
    for (int kc = 0; kc < 5; kc++) {
        int tlo = 2*kc, thi = 2*kc + 1;
        uint4 A[4];
        #pragma unroll
        for (int mt = 0; mt < 4; mt++)
            A[mt] = __ldg(&g_w1f[(kc*4 + mt)*32 + lane]);
        int blo = (ly + tlo/3)*34 + tlo%3 + gid;
        if (thi <= 8) {
            int bhi = (ly + thi/3)*34 + thi%3 + gid;
            #pragma unroll
            for (int nt = 0; nt < 4; nt++) {
                uint32_t b0 = sp[(blo + nt*8)*4 + tig];
                uint32_t b1 = sp[(bhi + nt*8)*4 + tig];
                #pragma unroll
                for (int mt = 0; mt < 4; mt++)
                    mma_bf16(acc[mt][nt], A[mt].x, A[mt].y, A[mt].z, A[mt].w, b0, b1);
            }
        } else {
            #pragma unroll
            for (int nt = 0; nt < 4; nt++) {
                uint32_t b0 = sp[(blo + nt*8)*4 + tig];
                #pragma unroll
                for (int mt = 0; mt < 4; mt++)
                    mma_bf16(acc[mt][nt], A[mt].x, A[mt].y, A[mt].z, A[mt].w, b0, 0u);
            }
        }
    }

    __nv_bfloat16* dst = g_h1 + ((size_t)n * PLANE + (y0t + ly) * WF + x0t) * 64;
    #pragma unroll
    for (int mt = 0; mt < 4; mt++) {
        int oc0 = mt*16 + gid, oc1 = oc0 + 8;
        float bv0 = __ldg(&bias[oc0]), bv1 = __ldg(&bias[oc1]);
        #pragma unroll
        for (int nt = 0; nt < 4; nt++) {
            int px = nt*8 + 2*tig;
            dst[(size_t)px*64 + oc0]     = __float2bfloat16_rn(fmaxf(acc[mt][nt][0] + bv0, 0.f));
            dst[(size_t)(px+1)*64 + oc0] = __float2bfloat16_rn(fmaxf(acc[mt][nt][1] + bv0, 0.f));
            dst[(size_t)px*64 + oc1]     = __float2bfloat16_rn(fmaxf(acc[mt][nt][2] + bv1, 0.f));
            dst[(size_t)(px+1)*64 + oc1] = __float2bfloat16_rn(fmaxf(acc[mt][nt][3] + bv1, 0.f));
        }
    }
}

// ================= conv2: 64 -> 64, ReLU, bf16 MMA =================
// tile 32x8, 8 warps: warp = output row, M=64 per warp (mt 0..3), N=32 (nt 0..3)
__global__ void __launch_bounds__(256, 2) conv2_kernel(const float* __restrict__ bias)
{
    __shared__ uint4 s_in[340*9];  // [px 10x34][64ch bf16 = 8 uint4, pad to 9]

    const int tid = threadIdx.x;
    const int lane = tid & 31, ly = tid >> 5;
    const int gid = lane >> 2, tig = lane & 3;
    const int n = blockIdx.z;
    const int x0t = blockIdx.x * 32, y0t = blockIdx.y * 8;

    for (int i = tid; i < 340; i += 256) {
        int r = i / 34, c = i - r * 34;
        int gy = min(max(y0t - 1 + r, 0), HF - 1);
        int gx = min(max(x0t - 1 + c, 0), WF - 1);
        const uint4* src = (const uint4*)(g_h1 + ((size_t)n * PLANE + gy * WF + gx) * 64);
        uint4* dst = s_in + i * 9;
        #pragma unroll
        for (int j = 0; j < 8; j++) dst[j] = src[j];
    }
    __syncthreads();

    float acc[4][4][4] = {};
    const uint32_t* s32 = (const uint32_t*)s_in;

    for (int tap = 0; tap < 9; tap++) {
        int prow = (ly + tap/3)*34 + tap%3 + gid;
        #pragma unroll
        for (int kt = 0; kt < 4; kt++) {
            uint4 A[4];
            #pragma unroll
            for (int mt = 0; mt < 4; mt++)
                A[mt] = __ldg(&g_w2f[((tap*4 + kt)*4 + mt)*32 + lane]);
            #pragma unroll
            for (int nt = 0; nt < 4; nt++) {
                int w = (prow + nt*8)*36 + kt*8 + tig;
                uint32_t b0 = s32[w];
                uint32_t b1 = s32[w + 4];
                #pragma unroll
                for (int mt = 0; mt < 4; mt++)
                    mma_bf16(acc[mt][nt], A[mt].x, A[mt].y, A[mt].z, A[mt].w, b0, b1);
            }
        }
    }

    __nv_bfloat16* dst = g_h2 + ((size_t)n * PLANE + (y0t + ly) * WF + x0t) * 64;
    #pragma unroll
    for (int mt = 0; mt < 4; mt++) {
        int oc0 = mt*16 + gid, oc1 = oc0 + 8;
        float bv0 = __ldg(&bias[oc0]), bv1 = __ldg(&bias[oc1]);
        #pragma unroll
        for (int nt = 0; nt < 4; nt++) {
            int px = nt*8 + 2*tig;
            dst[(size_t)px*64 + oc0]     = __float2bfloat16_rn(fmaxf(acc[mt][nt][0] + bv0, 0.f));
            dst[(size_t)(px+1)*64 + oc0] = __float2bfloat16_rn(fmaxf(acc[mt][nt][1] + bv0, 0.f));
            dst[(size_t)px*64 + oc1]     = __float2bfloat16_rn(fmaxf(acc[mt][nt][2] + bv1, 0.f));
            dst[(size_t)(px+1)*64 + oc1] = __float2bfloat16_rn(fmaxf(acc[mt][nt][3] + bv1, 0.f));
        }
    }
}

// ================= conv3 (64->2) + blend/clamp epilogue =================
#define C3_SMEM (324*9*16 + 1152*4)

__global__ void __launch_bounds__(256) conv3ep_kernel(const float* __restrict__ bias,
                                                      float* __restrict__ out, int t)
{
    extern __shared__ char cm[];
    uint4* s_h2 = (uint4*)cm;                       // [18x18 px][8 uint4 pad 9]
    float* s_w3 = (float*)(cm + 324*9*16);          // [tap][oc][ic]

    const int tid = threadIdx.y * 16 + threadIdx.x;
    const int n = blockIdx.z;
    const int x0t = blockIdx.x * 16, y0t = blockIdx.y * 16;

    for (int i = tid; i < 1152; i += 256) s_w3[i] = g_w3p[i];
    for (int i = tid; i < 324; i += 256) {
        int r = i / 18, c = i - r * 18;
        int gy = min(max(y0t - 1 + r, 0), HF - 1);
        int gx = min(max(x0t - 1 + c, 0), WF - 1);
        const uint4* src = (const uint4*)(g_h2 + ((size_t)n * PLANE + gy * WF + gx) * 64);
        uint4* dst = s_h2 + i * 9;
        #pragma unroll
        for (int j = 0; j < 8; j++) dst[j] = src[j];
    }
    __syncthreads();

    float r0 = __ldg(&bias[0]);
    float r1 = __ldg(&bias[1]);

    #pragma unroll
    for (int tap = 0; tap < 9; tap++) {
        int p = (threadIdx.y + tap/3) * 18 + threadIdx.x + tap%3;
        const uint4* pp = s_h2 + p * 9;
        const float* wa = s_w3 + tap * 128;
        const float* wb = wa + 64;
        #pragma unroll
        for (int q = 0; q < 8; q++) {
            uint4 v = pp[q];
            float2 f0 = __bfloat1622float2(*(__nv_bfloat162*)&v.x);
            float2 f1 = __bfloat1622float2(*(__nv_bfloat162*)&v.y);
            float2 f2 = __bfloat1622float2(*(__nv_bfloat162*)&v.z);
            float2 f3 = __bfloat1622float2(*(__nv_bfloat162*)&v.w);
            int k = q * 8;
            r0 += f0.x*wa[k]   + f0.y*wa[k+1] + f1.x*wa[k+2] + f1.y*wa[k+3]
                + f2.x*wa[k+4] + f2.y*wa[k+5] + f3.x*wa[k+6] + f3.y*wa[k+7];
            r1 += f0.x*wb[k]   + f0.y*wb[k+1] + f1.x*wb[k+2] + f1.y*wb[k+3]
                + f2.x*wb[k+4] + f2.y*wb[k+5] + f3.x*wb[k+6] + f3.y*wb[k+7];
        }
    }

    int x = x0t + threadIdx.x;
    int y = y0t + threadIdx.y;
    int o = y * WF + x;
    float alpha = fminf(fmaxf(r0, 0.0f), 1.0f);
    float4 h = g_hw4[n * PLANE + o];
    float4 f = g_fb4[n * PLANE + o];
    float ia = 1.0f - alpha;
    float n0 = fminf(fmaxf(h.x * ia + f.x * alpha, 0.f), 1.f);
    float n1 = fminf(fmaxf(h.y * ia + f.y * alpha, 0.f), 1.f);
    float n2 = fminf(fmaxf(h.z * ia + f.z * alpha, 0.f), 1.f);
    float n3 = fminf(fmaxf(h.w * ia + f.w * alpha + r1, 0.f), 1.f);

    g_ha[n * PLANE + o] = make_float4(n0, n1, n2, n3);
    float* op = out + ((size_t)(t * NB + n) * 3) * PLANE + o;
    op[0] = n0; op[PLANE] = n1; op[2*PLANE] = n2;
}

// ---------------- launch ----------------
extern "C" void kernel_launch(void* const* d_in, const int* in_sizes, int n_in,
                              void* d_out, int out_size)
{
    const float* frames = (const float*)d_in[0];
    const float* depths = (const float*)d_in[1];
    const float* mvs    = (const float*)d_in[2];
    const float* jits   = (const float*)d_in[3];
    const float* w1 = (const float*)d_in[4];
    const float* b1 = (const float*)d_in[5];
    const float* w2 = (const float*)d_in[6];
    const float* b2 = (const float*)d_in[7];
    const float* w3 = (const float*)d_in[8];
    const float* b3 = (const float*)d_in[9];
    float* out = (float*)d_out;

    cudaFuncSetAttribute(conv3ep_kernel, cudaFuncAttributeMaxDynamicSharedMemorySize, C3_SMEM);

    dim3 cgrid(WF/32, HF/8, NB);
    dim3 c3grid(WF/16, HF/16, NB);
    dim3 c3blk(16, 16);
    int pgrid = (NB*PLANE + 255) / 256;

    prepack_kernel<<<25, 256>>>(w1, w2, w3);

    for (int s = 0; s < Tt; s++) {
        int t = Tt - 1 - s;
        if (s == 0) {
            pre_kernel<<<pgrid, 256>>>(frames + (size_t)t * NB * 3 * SRC,
                                       depths + (size_t)t * NB * SRC,
                                       jits + (size_t)t * NB * 2);
        } else {
            prewarp_kernel<<<pgrid, 256>>>(frames + (size_t)t * NB * 3 * SRC,
                                           depths + (size_t)t * NB * SRC,
                                           jits + (size_t)t * NB * 2,
                                           mvs + (size_t)t * NB * SRC * 2);
        }
        conv1_kernel<<<cgrid, 256>>>(b1);
        conv2_kernel<<<cgrid, 256>>>(b2);
        conv3ep_kernel<<<c3grid, c3blk, C3_SMEM>>>(b3, out, t);
    }
}